// round 1
// baseline (speedup 1.0000x reference)
#include <cuda_runtime.h>

// RBF kernel: out[i,j] = exp(-(||x_i||^2 + ||y_j||^2 - 2 x_i.y_j)), clamped at 0.
// x: (8192, 256) f32, y: (8192, 256) f32, out: (8192, 8192) f32 row-major.

#define MDIM 8192
#define NDIM 8192
#define KDIM 256
#define BM 128
#define BN 128
#define BK 16
#define TM 8
#define TN 8

// Scratch for row norms (allocation-free per harness rules).
__device__ float g_x2[MDIM];
__device__ float g_y2[NDIM];

// One warp per row; 32 lanes * 2 float4 = 256 floats = K.
__global__ void rbf_rownorm_kernel(const float* __restrict__ x,
                                   const float* __restrict__ y) {
    int row = blockIdx.x;
    const float* p;
    float* outp;
    if (row < MDIM) {
        p = x + (size_t)row * KDIM;
        outp = &g_x2[row];
    } else {
        p = y + (size_t)(row - MDIM) * KDIM;
        outp = &g_y2[row - MDIM];
    }
    int lane = threadIdx.x;
    float4 a = ((const float4*)p)[lane];
    float4 b = ((const float4*)p)[lane + 32];
    float s = a.x * a.x + a.y * a.y + a.z * a.z + a.w * a.w
            + b.x * b.x + b.y * b.y + b.z * b.z + b.w * b.w;
    #pragma unroll
    for (int off = 16; off > 0; off >>= 1)
        s += __shfl_down_sync(0xffffffffu, s, off);
    if (lane == 0) *outp = s;
}

__global__ __launch_bounds__(256, 2)
void rbf_gemm_kernel(const float* __restrict__ X,
                     const float* __restrict__ Y,
                     float* __restrict__ out) {
    __shared__ float As[BK][BM];   // transposed: As[k][m]
    __shared__ float Bs[BK][BN];   // transposed: Bs[k][n]

    const int tid  = threadIdx.x;       // 0..255
    const int tx   = tid & 15;          // col group (16)
    const int ty   = tid >> 4;          // row group (16)
    const int row0 = blockIdx.y * BM;
    const int col0 = blockIdx.x * BN;

    float acc[TM][TN];
    #pragma unroll
    for (int i = 0; i < TM; i++)
        #pragma unroll
        for (int j = 0; j < TN; j++)
            acc[i][j] = 0.0f;

    for (int k0 = 0; k0 < KDIM; k0 += BK) {
        // Cooperative load: 128 rows x 16 k per tile = 512 float4 per matrix.
        // 256 threads -> 2 float4 each per matrix.
        #pragma unroll
        for (int it = 0; it < 2; it++) {
            int f  = tid + it * 256;   // 0..511
            int r  = f >> 2;           // row within tile (0..127)
            int kq = f & 3;            // which float4 along k (0..3)
            float4 va = *(const float4*)(X + (size_t)(row0 + r) * KDIM + k0 + kq * 4);
            As[kq * 4 + 0][r] = va.x;
            As[kq * 4 + 1][r] = va.y;
            As[kq * 4 + 2][r] = va.z;
            As[kq * 4 + 3][r] = va.w;
            float4 vb = *(const float4*)(Y + (size_t)(col0 + r) * KDIM + k0 + kq * 4);
            Bs[kq * 4 + 0][r] = vb.x;
            Bs[kq * 4 + 1][r] = vb.y;
            Bs[kq * 4 + 2][r] = vb.z;
            Bs[kq * 4 + 3][r] = vb.w;
        }
        __syncthreads();

        #pragma unroll
        for (int k = 0; k < BK; k++) {
            float a[TM], b[TN];
            #pragma unroll
            for (int i = 0; i < TM; i++) a[i] = As[k][ty * TM + i];
            #pragma unroll
            for (int j = 0; j < TN; j++) b[j] = Bs[k][tx * TN + j];
            #pragma unroll
            for (int i = 0; i < TM; i++)
                #pragma unroll
                for (int j = 0; j < TN; j++)
                    acc[i][j] = fmaf(a[i], b[j], acc[i][j]);
        }
        __syncthreads();
    }

    // Epilogue: sq = x2 + y2 - 2*dot; out = exp(-sq).
    // exp(-t) == 0.0f exactly for t > 104 (below smallest fp32 subnormal),
    // so predicate the MUFU away for the overwhelmingly common case.
    float x2r[TM], y2c[TN];
    #pragma unroll
    for (int i = 0; i < TM; i++) x2r[i] = g_x2[row0 + ty * TM + i];
    #pragma unroll
    for (int j = 0; j < TN; j++) y2c[j] = g_y2[col0 + tx * TN + j];

    #pragma unroll
    for (int i = 0; i < TM; i++) {
        float res[TN];
        #pragma unroll
        for (int j = 0; j < TN; j++) {
            float s = fmaf(-2.0f, acc[i][j], x2r[i] + y2c[j]);
            s = fmaxf(s, 0.0f);
            res[j] = (s > 104.0f) ? 0.0f : __expf(-s);
        }
        float* orow = out + (size_t)(row0 + ty * TM + i) * NDIM + col0 + tx * TN;
        *(float4*)(orow + 0) = make_float4(res[0], res[1], res[2], res[3]);
        *(float4*)(orow + 4) = make_float4(res[4], res[5], res[6], res[7]);
    }
}

extern "C" void kernel_launch(void* const* d_in, const int* in_sizes, int n_in,
                              void* d_out, int out_size) {
    const float* x = (const float*)d_in[0];
    const float* y = (const float*)d_in[1];
    float* out = (float*)d_out;

    rbf_rownorm_kernel<<<MDIM + NDIM, 32>>>(x, y);

    dim3 grid(NDIM / BN, MDIM / BM);   // 64 x 64
    rbf_gemm_kernel<<<grid, 256>>>(x, y, out);
}

// round 3
// speedup vs baseline: 3.7810x; 3.7810x over previous
#include <cuda_runtime.h>
#include <cuda_bf16.h>
#include <cstdint>

// RBF kernel: out[i,j] = exp(-max(||x_i||^2 + ||y_j||^2 - 2 x_i.y_j, 0))
// x,y: (8192, 256) f32. out: (8192, 8192) f32.
// sm_100 (non-'a') path: bf16 mma.sync (HMMA) + ldmatrix + cp.async.

#define MDIM 8192
#define NDIM 8192
#define KDIM 256
#define BM 128
#define BN 256
#define PITCH 264              // bf16 elems per smem row (256 + 8 pad) = 528 B
#define PITCHB (PITCH * 2)

// ---- scratch (allocation-free) ----
__device__ float g_x2[MDIM];
__device__ float g_y2[NDIM];
__device__ __nv_bfloat16 g_xb[(size_t)MDIM * KDIM];
__device__ __nv_bfloat16 g_yb[(size_t)NDIM * KDIM];

// smem layout (bytes, 16B-aligned chunks)
#define SM_A   0
#define SM_B   (BM * PITCHB)                 // 67584
#define SM_X2  (SM_B + BN * PITCHB)          // 67584 + 135168 = 202752
#define SM_Y2  (SM_X2 + BM * 4)              // + 512
#define SM_TOT (SM_Y2 + BN * 4)              // + 1024 = 204288

__device__ __forceinline__ uint32_t smem_u32(const void* p) {
    uint32_t a;
    asm("{ .reg .u64 t; cvta.to.shared.u64 t, %1; cvt.u32.u64 %0, t; }" : "=r"(a) : "l"(p));
    return a;
}

__device__ __forceinline__ void cp_async16(uint32_t saddr, const void* gaddr) {
    asm volatile("cp.async.cg.shared.global [%0], [%1], 16;" :: "r"(saddr), "l"(gaddr));
}

__device__ __forceinline__ void ldmatrix_x4(uint32_t& r0, uint32_t& r1,
                                            uint32_t& r2, uint32_t& r3, uint32_t addr) {
    asm volatile("ldmatrix.sync.aligned.m8n8.x4.shared.b16 {%0,%1,%2,%3}, [%4];"
                 : "=r"(r0), "=r"(r1), "=r"(r2), "=r"(r3) : "r"(addr));
}

__device__ __forceinline__ void mma_bf16(float& c0, float& c1, float& c2, float& c3,
                                         uint32_t a0, uint32_t a1, uint32_t a2, uint32_t a3,
                                         uint32_t b0, uint32_t b1) {
    asm volatile(
        "mma.sync.aligned.m16n8k16.row.col.f32.bf16.bf16.f32 "
        "{%0,%1,%2,%3}, {%4,%5,%6,%7}, {%8,%9}, {%0,%1,%2,%3};"
        : "+f"(c0), "+f"(c1), "+f"(c2), "+f"(c3)
        : "r"(a0), "r"(a1), "r"(a2), "r"(a3), "r"(b0), "r"(b1));
}

// ---- prep: fp32 -> bf16 + row norms. One warp per row. ----
__global__ void rbf_prep_kernel(const float* __restrict__ x,
                                const float* __restrict__ y) {
    int row = blockIdx.x;
    const float* src;
    __nv_bfloat16* dst;
    float* np;
    if (row < MDIM) {
        src = x + (size_t)row * KDIM; dst = g_xb + (size_t)row * KDIM; np = &g_x2[row];
    } else {
        row -= MDIM;
        src = y + (size_t)row * KDIM; dst = g_yb + (size_t)row * KDIM; np = &g_y2[row];
    }
    int lane = threadIdx.x;
    float4 a = ((const float4*)src)[lane];
    float4 b = ((const float4*)src)[lane + 32];
    __nv_bfloat162* d2 = (__nv_bfloat162*)dst;
    d2[lane * 2 + 0]      = __float22bfloat162_rn(make_float2(a.x, a.y));
    d2[lane * 2 + 1]      = __float22bfloat162_rn(make_float2(a.z, a.w));
    d2[64 + lane * 2 + 0] = __float22bfloat162_rn(make_float2(b.x, b.y));
    d2[64 + lane * 2 + 1] = __float22bfloat162_rn(make_float2(b.z, b.w));
    float s = a.x * a.x + a.y * a.y + a.z * a.z + a.w * a.w
            + b.x * b.x + b.y * b.y + b.z * b.z + b.w * b.w;
    #pragma unroll
    for (int off = 16; off > 0; off >>= 1)
        s += __shfl_down_sync(0xffffffffu, s, off);
    if (lane == 0) *np = s;
}

// ---- main: one 128x256 tile per CTA, 8 warps (2x4), warp tile 64x64 ----
__global__ void __launch_bounds__(256, 1)
rbf_mma_kernel(float* __restrict__ out) {
    extern __shared__ char sm[];
    const uint32_t sbase = smem_u32(sm);

    const int tid  = threadIdx.x;
    const int wid  = tid >> 5;
    const int lane = tid & 31;
    const int row0 = blockIdx.y * BM;
    const int col0 = blockIdx.x * BN;

    // ---- stage A (128x256), B (256x256) bf16 tiles + norms via cp.async ----
    #pragma unroll
    for (int it = 0; it < (BM * 32) / 256; it++) {     // 16 chunks/thread
        int idx = it * 256 + tid;
        int r = idx >> 5, q = idx & 31;
        cp_async16(sbase + SM_A + r * PITCHB + q * 16,
                   &g_xb[(size_t)(row0 + r) * KDIM + q * 8]);
    }
    #pragma unroll
    for (int it = 0; it < (BN * 32) / 256; it++) {     // 32 chunks/thread
        int idx = it * 256 + tid;
        int r = idx >> 5, q = idx & 31;
        cp_async16(sbase + SM_B + r * PITCHB + q * 16,
                   &g_yb[(size_t)(col0 + r) * KDIM + q * 8]);
    }
    if (tid < BM) ((float*)(sm + SM_X2))[tid] = g_x2[row0 + tid];
    ((float*)(sm + SM_Y2))[tid] = g_y2[col0 + tid];
    asm volatile("cp.async.commit_group;");
    asm volatile("cp.async.wait_group 0;" ::: "memory");
    __syncthreads();

    // ---- warp tiling ----
    const int wr = wid >> 2;          // 0..1  (M groups of 64)
    const int wc = wid & 3;           // 0..3  (N groups of 64)
    const int m_base = wr * 64;
    const int n_base = wc * 64;

    // ldmatrix lane base addresses
    // A, mtile i: rows m_base+i*16+(lane&15), col half (lane>>4)*8
    uint32_t a_addr[4];
    #pragma unroll
    for (int i = 0; i < 4; i++)
        a_addr[i] = sbase + SM_A + (m_base + i * 16 + (lane & 15)) * PITCHB
                  + (lane >> 4) * 16;
    // B, pair p: rows n_base+p*16+(lane>>4)*8+(lane&7), k half ((lane>>3)&1)*8
    uint32_t b_addr[4];
    #pragma unroll
    for (int p = 0; p < 4; p++)
        b_addr[p] = sbase + SM_B + (n_base + p * 16 + (lane >> 4) * 8 + (lane & 7)) * PITCHB
                  + ((lane >> 3) & 1) * 16;

    float c[4][8][4];
    #pragma unroll
    for (int i = 0; i < 4; i++)
        #pragma unroll
        for (int j = 0; j < 8; j++)
            #pragma unroll
            for (int v = 0; v < 4; v++) c[i][j][v] = 0.0f;

    #pragma unroll
    for (int ks = 0; ks < KDIM / 16; ks++) {
        const uint32_t koff = ks * 32;           // 16 bf16 = 32 bytes
        uint32_t a[4][4];
        #pragma unroll
        for (int i = 0; i < 4; i++)
            ldmatrix_x4(a[i][0], a[i][1], a[i][2], a[i][3], a_addr[i] + koff);
        #pragma unroll
        for (int p = 0; p < 4; p++) {
            uint32_t b0, b1, b2, b3;
            ldmatrix_x4(b0, b1, b2, b3, b_addr[p] + koff);
            #pragma unroll
            for (int i = 0; i < 4; i++) {
                mma_bf16(c[i][2 * p + 0][0], c[i][2 * p + 0][1],
                         c[i][2 * p + 0][2], c[i][2 * p + 0][3],
                         a[i][0], a[i][1], a[i][2], a[i][3], b0, b1);
                mma_bf16(c[i][2 * p + 1][0], c[i][2 * p + 1][1],
                         c[i][2 * p + 1][2], c[i][2 * p + 1][3],
                         a[i][0], a[i][1], a[i][2], a[i][3], b2, b3);
            }
        }
    }

    // ---- epilogue: s = x2 + y2 - 2*dot; out = (s>104) ? 0 : exp(-s) ----
    const float* x2s = (const float*)(sm + SM_X2);
    const float* y2s = (const float*)(sm + SM_Y2);
    const int g   = lane >> 2;
    const int nco = (lane & 3) * 2;

    #pragma unroll
    for (int i = 0; i < 4; i++) {
        const int mr0 = m_base + i * 16 + g;
        const float x2a = x2s[mr0];
        const float x2b = x2s[mr0 + 8];
        float* orow_a = out + (size_t)(row0 + mr0) * NDIM + col0;
        float* orow_b = orow_a + (size_t)8 * NDIM;
        #pragma unroll
        for (int j = 0; j < 8; j++) {
            const int nc = n_base + j * 8 + nco;
            const float y20 = y2s[nc], y21 = y2s[nc + 1];
            float s0 = fmaxf(fmaf(-2.0f, c[i][j][0], x2a + y20), 0.0f);
            float s1 = fmaxf(fmaf(-2.0f, c[i][j][1], x2a + y21), 0.0f);
            float s2 = fmaxf(fmaf(-2.0f, c[i][j][2], x2b + y20), 0.0f);
            float s3 = fmaxf(fmaf(-2.0f, c[i][j][3], x2b + y21), 0.0f);
            float2 oa, ob;
            oa.x = (s0 > 104.0f) ? 0.0f : __expf(-s0);
            oa.y = (s1 > 104.0f) ? 0.0f : __expf(-s1);
            ob.x = (s2 > 104.0f) ? 0.0f : __expf(-s2);
            ob.y = (s3 > 104.0f) ? 0.0f : __expf(-s3);
            *(float2*)(orow_a + nc) = oa;
            *(float2*)(orow_b + nc) = ob;
        }
    }
}

extern "C" void kernel_launch(void* const* d_in, const int* in_sizes, int n_in,
                              void* d_out, int out_size) {
    const float* x = (const float*)d_in[0];
    const float* y = (const float*)d_in[1];
    float* out = (float*)d_out;

    cudaFuncSetAttribute(rbf_mma_kernel,
                         cudaFuncAttributeMaxDynamicSharedMemorySize, SM_TOT);

    rbf_prep_kernel<<<MDIM + NDIM, 32>>>(x, y);

    dim3 grid(NDIM / BN, MDIM / BM);   // (32, 64)
    rbf_mma_kernel<<<grid, 256, SM_TOT>>>(out);
}

// round 4
// speedup vs baseline: 4.4677x; 1.1816x over previous
#include <cuda_runtime.h>
#include <cuda_bf16.h>
#include <cstdint>

// RBF kernel: out[i,j] = exp(-max(||x_i||^2 + ||y_j||^2 - 2 x_i.y_j, 0))
// x,y: (8192, 256) f32. out: (8192, 8192) f32.
// bf16 mma.sync (HMMA) + ldmatrix + 3-stage cp.async K-pipeline.

#define MDIM 8192
#define NDIM 8192
#define KDIM 256
#define BM 128
#define BN 256
#define BK 64
#define NCHUNK (KDIM / BK)      // 4
#define PITCH 72                // bf16 elems per smem row (64 + 8 pad) = 144 B
#define PITCHB (PITCH * 2)
#define STAGE_BYTES ((BM + BN) * PITCHB)   // 55296
#define NSTAGE 3

// ---- scratch (allocation-free) ----
__device__ float g_x2[MDIM];
__device__ float g_y2[NDIM];
__device__ __nv_bfloat16 g_xb[(size_t)MDIM * KDIM];
__device__ __nv_bfloat16 g_yb[(size_t)NDIM * KDIM];

// smem layout (bytes)
#define SM_TILES 0
#define SM_X2    (NSTAGE * STAGE_BYTES)          // 165888
#define SM_Y2    (SM_X2 + BM * 4)                // +512
#define SM_TOT   (SM_Y2 + BN * 4)                // +1024 = 167424

__device__ __forceinline__ uint32_t smem_u32(const void* p) {
    uint32_t a;
    asm("{ .reg .u64 t; cvta.to.shared.u64 t, %1; cvt.u32.u64 %0, t; }" : "=r"(a) : "l"(p));
    return a;
}

__device__ __forceinline__ void cp_async16(uint32_t saddr, const void* gaddr) {
    asm volatile("cp.async.cg.shared.global [%0], [%1], 16;" :: "r"(saddr), "l"(gaddr));
}

__device__ __forceinline__ void ldmatrix_x4(uint32_t& r0, uint32_t& r1,
                                            uint32_t& r2, uint32_t& r3, uint32_t addr) {
    asm volatile("ldmatrix.sync.aligned.m8n8.x4.shared.b16 {%0,%1,%2,%3}, [%4];"
                 : "=r"(r0), "=r"(r1), "=r"(r2), "=r"(r3) : "r"(addr));
}

__device__ __forceinline__ void mma_bf16(float& c0, float& c1, float& c2, float& c3,
                                         uint32_t a0, uint32_t a1, uint32_t a2, uint32_t a3,
                                         uint32_t b0, uint32_t b1) {
    asm volatile(
        "mma.sync.aligned.m16n8k16.row.col.f32.bf16.bf16.f32 "
        "{%0,%1,%2,%3}, {%4,%5,%6,%7}, {%8,%9}, {%0,%1,%2,%3};"
        : "+f"(c0), "+f"(c1), "+f"(c2), "+f"(c3)
        : "r"(a0), "r"(a1), "r"(a2), "r"(a3), "r"(b0), "r"(b1));
}

// ---- prep: fp32 -> bf16 + row norms. One warp per row. ----
__global__ void rbf_prep_kernel(const float* __restrict__ x,
                                const float* __restrict__ y) {
    int row = blockIdx.x;
    const float* src;
    __nv_bfloat16* dst;
    float* np;
    if (row < MDIM) {
        src = x + (size_t)row * KDIM; dst = g_xb + (size_t)row * KDIM; np = &g_x2[row];
    } else {
        row -= MDIM;
        src = y + (size_t)row * KDIM; dst = g_yb + (size_t)row * KDIM; np = &g_y2[row];
    }
    int lane = threadIdx.x;
    float4 a = ((const float4*)src)[lane];
    float4 b = ((const float4*)src)[lane + 32];
    __nv_bfloat162* d2 = (__nv_bfloat162*)dst;
    d2[lane * 2 + 0]      = __float22bfloat162_rn(make_float2(a.x, a.y));
    d2[lane * 2 + 1]      = __float22bfloat162_rn(make_float2(a.z, a.w));
    d2[64 + lane * 2 + 0] = __float22bfloat162_rn(make_float2(b.x, b.y));
    d2[64 + lane * 2 + 1] = __float22bfloat162_rn(make_float2(b.z, b.w));
    float s = a.x * a.x + a.y * a.y + a.z * a.z + a.w * a.w
            + b.x * b.x + b.y * b.y + b.z * b.z + b.w * b.w;
    #pragma unroll
    for (int off = 16; off > 0; off >>= 1)
        s += __shfl_down_sync(0xffffffffu, s, off);
    if (lane == 0) *np = s;
}

// ---- main: 128x256 tile per CTA, 16 warps (2x8), warp tile 64x32 ----
__global__ void __launch_bounds__(512, 1)
rbf_mma_kernel(float* __restrict__ out) {
    extern __shared__ char sm[];
    const uint32_t sbase = smem_u32(sm);

    const int tid  = threadIdx.x;
    const int wid  = tid >> 5;
    const int lane = tid & 31;
    const int row0 = blockIdx.y * BM;
    const int col0 = blockIdx.x * BN;

    // chunk loader: A (128x64) = 1024 16B-chunks, B (256x64) = 2048 chunks;
    // 512 threads -> 2 A-chunks + 4 B-chunks each.
    auto load_chunk = [&](int kc, int st) {
        const uint32_t abase = sbase + SM_TILES + st * STAGE_BYTES;
        const uint32_t bbase = abase + BM * PITCHB;
        const int gk = kc * BK;
        #pragma unroll
        for (int it = 0; it < 2; it++) {
            int idx = it * 512 + tid;
            int r = idx >> 3, q = idx & 7;
            cp_async16(abase + r * PITCHB + q * 16,
                       &g_xb[(size_t)(row0 + r) * KDIM + gk + q * 8]);
        }
        #pragma unroll
        for (int it = 0; it < 4; it++) {
            int idx = it * 512 + tid;
            int r = idx >> 3, q = idx & 7;
            cp_async16(bbase + r * PITCHB + q * 16,
                       &g_yb[(size_t)(col0 + r) * KDIM + gk + q * 8]);
        }
    };

    // norms into smem
    if (tid < BM) ((float*)(sm + SM_X2))[tid] = g_x2[row0 + tid];
    if (tid < BN) ((float*)(sm + SM_Y2))[tid] = g_y2[col0 + tid];

    // prologue: fill 3 stages
    load_chunk(0, 0); asm volatile("cp.async.commit_group;");
    load_chunk(1, 1); asm volatile("cp.async.commit_group;");
    load_chunk(2, 2); asm volatile("cp.async.commit_group;");

    // warp tiling: 2 x 8 warps, warp tile 64 x 32
    const int wr = wid >> 3;          // 0..1
    const int wc = wid & 7;           // 0..7
    const int m_base = wr * 64;
    const int n_base = wc * 32;

    // ldmatrix lane offsets (relative to stage base)
    uint32_t a_off[4];
    #pragma unroll
    for (int i = 0; i < 4; i++)
        a_off[i] = (m_base + i * 16 + (lane & 15)) * PITCHB + (lane >> 4) * 16;
    uint32_t b_off[2];
    #pragma unroll
    for (int p = 0; p < 2; p++)
        b_off[p] = BM * PITCHB
                 + (n_base + p * 16 + (lane >> 4) * 8 + (lane & 7)) * PITCHB
                 + ((lane >> 3) & 1) * 16;

    float c[4][4][4];
    #pragma unroll
    for (int i = 0; i < 4; i++)
        #pragma unroll
        for (int j = 0; j < 4; j++)
            #pragma unroll
            for (int v = 0; v < 4; v++) c[i][j][v] = 0.0f;

    for (int kc = 0; kc < NCHUNK; kc++) {
        asm volatile("cp.async.wait_group 2;" ::: "memory");
        __syncthreads();

        const uint32_t stbase = sbase + SM_TILES + (kc % NSTAGE) * STAGE_BYTES;
        #pragma unroll
        for (int ks = 0; ks < BK / 16; ks++) {
            const uint32_t koff = ks * 32;
            uint32_t a[4][4];
            #pragma unroll
            for (int i = 0; i < 4; i++)
                ldmatrix_x4(a[i][0], a[i][1], a[i][2], a[i][3],
                            stbase + a_off[i] + koff);
            #pragma unroll
            for (int p = 0; p < 2; p++) {
                uint32_t b0, b1, b2, b3;
                ldmatrix_x4(b0, b1, b2, b3, stbase + b_off[p] + koff);
                #pragma unroll
                for (int i = 0; i < 4; i++) {
                    mma_bf16(c[i][2 * p + 0][0], c[i][2 * p + 0][1],
                             c[i][2 * p + 0][2], c[i][2 * p + 0][3],
                             a[i][0], a[i][1], a[i][2], a[i][3], b0, b1);
                    mma_bf16(c[i][2 * p + 1][0], c[i][2 * p + 1][1],
                             c[i][2 * p + 1][2], c[i][2 * p + 1][3],
                             a[i][0], a[i][1], a[i][2], a[i][3], b2, b3);
                }
            }
        }
        __syncthreads();

        if (kc + NSTAGE < NCHUNK) load_chunk(kc + NSTAGE, kc % NSTAGE);
        asm volatile("cp.async.commit_group;");   // one commit per iter (may be empty)
    }

    // ---- epilogue ----
    const float* x2s = (const float*)(sm + SM_X2);
    const float* y2s = (const float*)(sm + SM_Y2);
    const int g   = lane >> 2;
    const int nco = (lane & 3) * 2;

    #pragma unroll
    for (int i = 0; i < 4; i++) {
        const int mr0 = m_base + i * 16 + g;
        const float x2a = x2s[mr0];
        const float x2b = x2s[mr0 + 8];
        float* orow_a = out + (size_t)(row0 + mr0) * NDIM + col0;
        float* orow_b = orow_a + (size_t)8 * NDIM;
        #pragma unroll
        for (int j = 0; j < 4; j++) {
            const int nc = n_base + j * 8 + nco;
            const float y20 = y2s[nc], y21 = y2s[nc + 1];
            float s0 = fmaxf(fmaf(-2.0f, c[i][j][0], x2a + y20), 0.0f);
            float s1 = fmaxf(fmaf(-2.0f, c[i][j][1], x2a + y21), 0.0f);
            float s2 = fmaxf(fmaf(-2.0f, c[i][j][2], x2b + y20), 0.0f);
            float s3 = fmaxf(fmaf(-2.0f, c[i][j][3], x2b + y21), 0.0f);
            float2 oa, ob;
            oa.x = (s0 > 104.0f) ? 0.0f : __expf(-s0);
            oa.y = (s1 > 104.0f) ? 0.0f : __expf(-s1);
            ob.x = (s2 > 104.0f) ? 0.0f : __expf(-s2);
            ob.y = (s3 > 104.0f) ? 0.0f : __expf(-s3);
            *(float2*)(orow_a + nc) = oa;
            *(float2*)(orow_b + nc) = ob;
        }
    }
}

extern "C" void kernel_launch(void* const* d_in, const int* in_sizes, int n_in,
                              void* d_out, int out_size) {
    const float* x = (const float*)d_in[0];
    const float* y = (const float*)d_in[1];
    float* out = (float*)d_out;

    cudaFuncSetAttribute(rbf_mma_kernel,
                         cudaFuncAttributeMaxDynamicSharedMemorySize, SM_TOT);

    rbf_prep_kernel<<<MDIM + NDIM, 32>>>(x, y);

    dim3 grid(NDIM / BN, MDIM / BM);   // (32, 64)
    rbf_mma_kernel<<<grid, 512, SM_TOT>>>(out);
}

// round 7
// speedup vs baseline: 6.0664x; 1.3578x over previous
#include <cuda_runtime.h>
#include <cuda_bf16.h>
#include <cstdint>

// RBF kernel: out[i,j] = exp(-max(||x_i||^2 + ||y_j||^2 - 2 x_i.y_j, 0))
// x,y: (8192, 256) f32. out: (8192, 8192) f32.
// bf16 mma.sync + ldmatrix + 2-stage cp.async pipeline, 2 CTAs/SM.

#define MDIM 8192
#define NDIM 8192
#define KDIM 256
#define BM 128
#define BN 128
#define BK 64
#define NCHUNK (KDIM / BK)      // 4
#define PITCH 72                // bf16 elems per smem row (64 + 8 pad) = 144 B
#define PITCHB (PITCH * 2)
#define STAGE_BYTES ((BM + BN) * PITCHB)   // 36864
#define NSTAGE 2

// ---- scratch (allocation-free) ----
__device__ float g_x2[MDIM];
__device__ float g_y2[NDIM];
__device__ __nv_bfloat16 g_xb[(size_t)MDIM * KDIM];
__device__ __nv_bfloat16 g_yb[(size_t)NDIM * KDIM];

// smem layout (bytes)
#define SM_X2    (NSTAGE * STAGE_BYTES)          // 73728
#define SM_Y2    (SM_X2 + BM * 4)                // +512
#define SM_TOT   (SM_Y2 + BN * 4)                // +512 = 74752

__device__ __forceinline__ uint32_t smem_u32(const void* p) {
    uint32_t a;
    asm("{ .reg .u64 t; cvta.to.shared.u64 t, %1; cvt.u32.u64 %0, t; }" : "=r"(a) : "l"(p));
    return a;
}

__device__ __forceinline__ void cp_async16(uint32_t saddr, const void* gaddr) {
    asm volatile("cp.async.cg.shared.global [%0], [%1], 16;" :: "r"(saddr), "l"(gaddr));
}

__device__ __forceinline__ void ldmatrix_x4(uint32_t& r0, uint32_t& r1,
                                            uint32_t& r2, uint32_t& r3, uint32_t addr) {
    asm volatile("ldmatrix.sync.aligned.m8n8.x4.shared.b16 {%0,%1,%2,%3}, [%4];"
                 : "=r"(r0), "=r"(r1), "=r"(r2), "=r"(r3) : "r"(addr));
}

__device__ __forceinline__ void mma_bf16(float& c0, float& c1, float& c2, float& c3,
                                         uint32_t a0, uint32_t a1, uint32_t a2, uint32_t a3,
                                         uint32_t b0, uint32_t b1) {
    asm volatile(
        "mma.sync.aligned.m16n8k16.row.col.f32.bf16.bf16.f32 "
        "{%0,%1,%2,%3}, {%4,%5,%6,%7}, {%8,%9}, {%0,%1,%2,%3};"
        : "+f"(c0), "+f"(c1), "+f"(c2), "+f"(c3)
        : "r"(a0), "r"(a1), "r"(a2), "r"(a3), "r"(b0), "r"(b1));
}

// ---- prep: fp32 -> bf16 + row norms. One warp per row. ----
__global__ void rbf_prep_kernel(const float* __restrict__ x,
                                const float* __restrict__ y) {
    int row = blockIdx.x;
    const float* src;
    __nv_bfloat16* dst;
    float* np;
    if (row < MDIM) {
        src = x + (size_t)row * KDIM; dst = g_xb + (size_t)row * KDIM; np = &g_x2[row];
    } else {
        row -= MDIM;
        src = y + (size_t)row * KDIM; dst = g_yb + (size_t)row * KDIM; np = &g_y2[row];
    }
    int lane = threadIdx.x;
    float4 a = ((const float4*)src)[lane];
    float4 b = ((const float4*)src)[lane + 32];
    __nv_bfloat162* d2 = (__nv_bfloat162*)dst;
    d2[lane * 2 + 0]      = __float22bfloat162_rn(make_float2(a.x, a.y));
    d2[lane * 2 + 1]      = __float22bfloat162_rn(make_float2(a.z, a.w));
    d2[64 + lane * 2 + 0] = __float22bfloat162_rn(make_float2(b.x, b.y));
    d2[64 + lane * 2 + 1] = __float22bfloat162_rn(make_float2(b.z, b.w));
    float s = a.x * a.x + a.y * a.y + a.z * a.z + a.w * a.w
            + b.x * b.x + b.y * b.y + b.z * b.z + b.w * b.w;
    #pragma unroll
    for (int off = 16; off > 0; off >>= 1)
        s += __shfl_down_sync(0xffffffffu, s, off);
    if (lane == 0) *np = s;
}

// ---- main: 128x128 tile per CTA, 8 warps (2x4), warp tile 64x32, 2 CTA/SM ----
__global__ void __launch_bounds__(256, 2)
rbf_mma_kernel(float* __restrict__ out) {
    extern __shared__ char sm[];
    const uint32_t sbase = smem_u32(sm);

    const int tid  = threadIdx.x;
    const int wid  = tid >> 5;
    const int lane = tid & 31;
    const int row0 = blockIdx.y * BM;
    const int col0 = blockIdx.x * BN;

    // chunk loader: A (128x64) = 1024 16B-chunks, B (128x64) = 1024 chunks;
    // 256 threads -> 4 A-chunks + 4 B-chunks each.
    auto load_chunk = [&](int kc, int st) {
        const uint32_t abase = sbase + st * STAGE_BYTES;
        const uint32_t bbase = abase + BM * PITCHB;
        const int gk = kc * BK;
        #pragma unroll
        for (int it = 0; it < 4; it++) {
            int idx = it * 256 + tid;
            int r = idx >> 3, q = idx & 7;
            cp_async16(abase + r * PITCHB + q * 16,
                       &g_xb[(size_t)(row0 + r) * KDIM + gk + q * 8]);
        }
        #pragma unroll
        for (int it = 0; it < 4; it++) {
            int idx = it * 256 + tid;
            int r = idx >> 3, q = idx & 7;
            cp_async16(bbase + r * PITCHB + q * 16,
                       &g_yb[(size_t)(col0 + r) * KDIM + gk + q * 8]);
        }
    };

    // norms into smem
    if (tid < BM) ((float*)(sm + SM_X2))[tid] = g_x2[row0 + tid];
    if (tid < BN) ((float*)(sm + SM_Y2))[tid] = g_y2[col0 + tid];

    // prologue: fill both stages
    load_chunk(0, 0); asm volatile("cp.async.commit_group;");
    load_chunk(1, 1); asm volatile("cp.async.commit_group;");

    // warp tiling: 2 x 4 warps, warp tile 64 x 32
    const int wr = wid >> 2;          // 0..1
    const int wc = wid & 3;           // 0..3
    const int m_base = wr * 64;
    const int n_base = wc * 32;

    // ldmatrix lane offsets (relative to stage base)
    uint32_t a_off[4];
    #pragma unroll
    for (int i = 0; i < 4; i++)
        a_off[i] = (m_base + i * 16 + (lane & 15)) * PITCHB + (lane >> 4) * 16;
    uint32_t b_off[2];
    #pragma unroll
    for (int p = 0; p < 2; p++)
        b_off[p] = BM * PITCHB
                 + (n_base + p * 16 + (lane >> 4) * 8 + (lane & 7)) * PITCHB
                 + ((lane >> 3) & 1) * 16;

    float c[4][4][4];
    #pragma unroll
    for (int i = 0; i < 4; i++)
        #pragma unroll
        for (int j = 0; j < 4; j++)
            #pragma unroll
            for (int v = 0; v < 4; v++) c[i][j][v] = 0.0f;

    for (int kc = 0; kc < NCHUNK; kc++) {
        asm volatile("cp.async.wait_group 1;" ::: "memory");
        __syncthreads();

        const uint32_t stbase = sbase + (kc % NSTAGE) * STAGE_BYTES;
        #pragma unroll
        for (int ks = 0; ks < BK / 16; ks++) {
            const uint32_t koff = ks * 32;
            uint32_t a[4][4];
            #pragma unroll
            for (int i = 0; i < 4; i++)
                ldmatrix_x4(a[i][0], a[i][1], a[i][2], a[i][3],
                            stbase + a_off[i] + koff);
            #pragma unroll
            for (int p = 0; p < 2; p++) {
                uint32_t b0, b1, b2, b3;
                ldmatrix_x4(b0, b1, b2, b3, stbase + b_off[p] + koff);
                #pragma unroll
                for (int i = 0; i < 4; i++) {
                    mma_bf16(c[i][2 * p + 0][0], c[i][2 * p + 0][1],
                             c[i][2 * p + 0][2], c[i][2 * p + 0][3],
                             a[i][0], a[i][1], a[i][2], a[i][3], b0, b1);
                    mma_bf16(c[i][2 * p + 1][0], c[i][2 * p + 1][1],
                             c[i][2 * p + 1][2], c[i][2 * p + 1][3],
                             a[i][0], a[i][1], a[i][2], a[i][3], b2, b3);
                }
            }
        }
        __syncthreads();

        if (kc + NSTAGE < NCHUNK) load_chunk(kc + NSTAGE, kc % NSTAGE);
        asm volatile("cp.async.commit_group;");   // one commit per iter (may be empty)
    }

    // ---- epilogue ----
    const float* x2s = (const float*)(sm + SM_X2);
    const float* y2s = (const float*)(sm + SM_Y2);
    const int g   = lane >> 2;
    const int nco = (lane & 3) * 2;

    #pragma unroll
    for (int i = 0; i < 4; i++) {
        const int mr0 = m_base + i * 16 + g;
        const float x2a = x2s[mr0];
        const float x2b = x2s[mr0 + 8];
        float* orow_a = out + (size_t)(row0 + mr0) * NDIM + col0;
        float* orow_b = orow_a + (size_t)8 * NDIM;
        #pragma unroll
        for (int j = 0; j < 4; j++) {
            const int nc = n_base + j * 8 + nco;
            const float y20 = y2s[nc], y21 = y2s[nc + 1];
            float s0 = fmaxf(fmaf(-2.0f, c[i][j][0], x2a + y20), 0.0f);
            float s1 = fmaxf(fmaf(-2.0f, c[i][j][1], x2a + y21), 0.0f);
            float s2 = fmaxf(fmaf(-2.0f, c[i][j][2], x2b + y20), 0.0f);
            float s3 = fmaxf(fmaf(-2.0f, c[i][j][3], x2b + y21), 0.0f);
            float2 oa, ob;
            oa.x = (s0 > 104.0f) ? 0.0f : __expf(-s0);
            oa.y = (s1 > 104.0f) ? 0.0f : __expf(-s1);
            ob.x = (s2 > 104.0f) ? 0.0f : __expf(-s2);
            ob.y = (s3 > 104.0f) ? 0.0f : __expf(-s3);
            *(float2*)(orow_a + nc) = oa;
            *(float2*)(orow_b + nc) = ob;
        }
    }
}

extern "C" void kernel_launch(void* const* d_in, const int* in_sizes, int n_in,
                              void* d_out, int out_size) {
    const float* x = (const float*)d_in[0];
    const float* y = (const float*)d_in[1];
    float* out = (float*)d_out;

    cudaFuncSetAttribute(rbf_mma_kernel,
                         cudaFuncAttributeMaxDynamicSharedMemorySize, SM_TOT);

    rbf_prep_kernel<<<MDIM + NDIM, 32>>>(x, y);

    dim3 grid(NDIM / BN, MDIM / BM);   // (64, 64)
    rbf_mma_kernel<<<grid, 256, SM_TOT>>>(out);
}